// round 7
// baseline (speedup 1.0000x reference)
#include <cuda_runtime.h>
#include <cuda_fp16.h>
#include <cstdint>

using f16 = __half;

// Problem dims
constexpr int BATCH    = 8192;
constexpr int IN_SIZE  = 4096;
constexpr int HIDDEN   = 4096;
constexpr int OUT_SIZE = 1024;

// GEMM tiling: CTA tile 256x128, warp tile 64x64, BK=64
constexpr int TM = 256;
constexpr int TN = 128;
constexpr int BK = 64;
constexpr int STAGES = 3;
constexpr int ROW_ELEMS  = 72;                    // 64 data + 8 pad f16 (144B pitch)
constexpr int A_ELEMS = TM * ROW_ELEMS;           // 18432
constexpr int B_ELEMS = TN * ROW_ELEMS;           // 9216
constexpr int STAGE_ELEMS = A_ELEMS + B_ELEMS;    // 27648
constexpr int SMEM_BYTES = STAGES * STAGE_ELEMS * 2;  // 165888 B

// ---------------- static device scratch ----------------
__device__ f16 g_w1s[HIDDEN * IN_SIZE];
__device__ f16 g_w2s[HIDDEN * HIDDEN];
__device__ f16 g_w3s[OUT_SIZE * HIDDEN];
__device__ f16 g_a[BATCH * IN_SIZE];
__device__ f16 g_b[BATCH * HIDDEN];
__device__ float g_part[3 * 2048];
__device__ float g_sum[3];

// ---------------- PTX helpers ----------------
__device__ __forceinline__ uint32_t sptr(const void* p) {
    return (uint32_t)__cvta_generic_to_shared(p);
}
__device__ __forceinline__ void cp16(const f16* dst_smem, const f16* src_gmem) {
    uint32_t d = sptr(dst_smem);
    asm volatile("cp.async.cg.shared.global [%0], [%1], 16;\n" :: "r"(d), "l"(src_gmem));
}
__device__ __forceinline__ void ldsm4(uint32_t* r, uint32_t addr) {
    asm volatile("ldmatrix.sync.aligned.m8n8.x4.shared.b16 {%0,%1,%2,%3}, [%4];"
                 : "=r"(r[0]), "=r"(r[1]), "=r"(r[2]), "=r"(r[3]) : "r"(addr));
}
// f16-accumulate variant: D,C are 2 regs (f16x2)
__device__ __forceinline__ void mma_f16acc(uint32_t* d, const uint32_t* a, const uint32_t* b) {
    asm volatile(
        "mma.sync.aligned.m16n8k16.row.col.f16.f16.f16.f16 "
        "{%0,%1}, {%2,%3,%4,%5}, {%6,%7}, {%0,%1};"
        : "+r"(d[0]), "+r"(d[1])
        : "r"(a[0]), "r"(a[1]), "r"(a[2]), "r"(a[3]), "r"(b[0]), "r"(b[1]));
}
// f32-accumulate variant (used for promotion)
__device__ __forceinline__ void mma_f32(float* d, const uint32_t* a, const uint32_t* b) {
    asm volatile(
        "mma.sync.aligned.m16n8k16.row.col.f32.f16.f16.f32 "
        "{%0,%1,%2,%3}, {%4,%5,%6,%7}, {%8,%9}, {%0,%1,%2,%3};"
        : "+f"(d[0]), "+f"(d[1]), "+f"(d[2]), "+f"(d[3])
        : "r"(a[0]), "r"(a[1]), "r"(a[2]), "r"(a[3]), "r"(b[0]), "r"(b[1]));
}

// ---------------- prep kernels ----------------
__global__ void sign_reduce_kernel(const float4* __restrict__ w4,
                                   __half2* __restrict__ ws2,
                                   int n4, int layer) {
    float s = 0.f;
    for (int i = blockIdx.x * blockDim.x + threadIdx.x; i < n4; i += gridDim.x * blockDim.x) {
        float4 v = w4[i];
        s += fabsf(v.x) + fabsf(v.y) + fabsf(v.z) + fabsf(v.w);
        f16 s0 = __float2half((v.x > 0.f) ? 1.f : ((v.x < 0.f) ? -1.f : 0.f));
        f16 s1 = __float2half((v.y > 0.f) ? 1.f : ((v.y < 0.f) ? -1.f : 0.f));
        f16 s2 = __float2half((v.z > 0.f) ? 1.f : ((v.z < 0.f) ? -1.f : 0.f));
        f16 s3 = __float2half((v.w > 0.f) ? 1.f : ((v.w < 0.f) ? -1.f : 0.f));
        ws2[2 * i]     = __halves2half2(s0, s1);
        ws2[2 * i + 1] = __halves2half2(s2, s3);
    }
    __shared__ float red[256];
    red[threadIdx.x] = s;
    __syncthreads();
    for (int o = 128; o > 0; o >>= 1) {
        if (threadIdx.x < o) red[threadIdx.x] += red[threadIdx.x + o];
        __syncthreads();
    }
    if (threadIdx.x == 0) g_part[layer * 2048 + blockIdx.x] = red[0];
}

__global__ void finalize_sum_kernel() {
    __shared__ float red[1024];
    int l = blockIdx.x, t = threadIdx.x;
    red[t] = g_part[l * 2048 + t] + g_part[l * 2048 + 1024 + t];
    __syncthreads();
    for (int o = 512; o > 0; o >>= 1) {
        if (t < o) red[t] += red[t + o];
        __syncthreads();
    }
    if (t == 0) g_sum[l] = red[0];
}

__global__ void convert_kernel(const float4* __restrict__ x4,
                               __half2* __restrict__ h2, int n4) {
    for (int i = blockIdx.x * blockDim.x + threadIdx.x; i < n4; i += gridDim.x * blockDim.x) {
        float4 v = x4[i];
        h2[2 * i]     = __halves2half2(__float2half(v.x), __float2half(v.y));
        h2[2 * i + 1] = __halves2half2(__float2half(v.z), __float2half(v.w));
    }
}

// ---------------- fused binarized GEMM (f16-accum chunks + HMMA promotion) ----------------
template <int EPI>
__global__ void __launch_bounds__(256, 1) gemm_bwn(
    const f16* __restrict__ A, const f16* __restrict__ Bs,
    const float* __restrict__ bias, const float* __restrict__ sumAbs, float invCnt,
    int K, int N,
    f16* __restrict__ oH, float* __restrict__ oF) {
    extern __shared__ f16 smem[];
    const int tid  = threadIdx.x;
    const int lane = tid & 31;
    const int warp = tid >> 5;
    const int wm = warp & 3;   // 4 warp-rows of 64
    const int wn = warp >> 2;  // 2 warp-cols of 64
    const int bm = blockIdx.y, bn = blockIdx.x;
    const int KT = K / BK;     // 64, divisible by 4

    const f16* gA = A  + (size_t)bm * TM * K;
    const f16* gB = Bs + (size_t)bn * TN * K;

    const int crow = tid >> 3;
    const int ccol = (tid & 7) * 8;

    auto issue = [&](int kt, int stage) {
        f16* sa = smem + stage * STAGE_ELEMS;
        f16* sb = sa + A_ELEMS;
        const int kof = kt * BK;
#pragma unroll
        for (int rr = 0; rr < 8; rr++) {
            const int row = rr * 32 + crow;
            cp16(sa + row * ROW_ELEMS + ccol, gA + (size_t)row * K + kof + ccol);
        }
#pragma unroll
        for (int rr = 0; rr < 4; rr++) {
            const int row = rr * 32 + crow;
            cp16(sb + row * ROW_ELEMS + ccol, gB + (size_t)row * K + kof + ccol);
        }
    };

    // f32 final accumulators + f16 chunk accumulators
    float acc[4][8][4];
    uint32_t ch[4][8][2];
#pragma unroll
    for (int i = 0; i < 4; i++)
#pragma unroll
        for (int j = 0; j < 8; j++) {
#pragma unroll
            for (int v = 0; v < 4; v++) acc[i][j][v] = 0.f;
            ch[i][j][0] = 0u; ch[i][j][1] = 0u;
        }

    // promotion B operand: B[k][n] = 1 iff (k&7)==n  (only k<8 half used; b1=0)
    uint32_t bId;
    {
        const int n = lane >> 2, k0 = (lane & 3) * 2;
        bId = ((k0 == n) ? 0x3C00u : 0u) | (((k0 + 1) == n) ? 0x3C000000u : 0u);
    }

    const int a_off = (wm * 64 + (lane & 15)) * ROW_ELEMS + (lane >> 4) * 8;
    const int b_off = (wn * 64 + ((lane >> 4) & 1) * 8 + (lane & 7)) * ROW_ELEMS
                    + ((lane >> 3) & 1) * 8;

    issue(0, 0);
    asm volatile("cp.async.commit_group;" ::: "memory");
    issue(1, 1);
    asm volatile("cp.async.commit_group;" ::: "memory");

    for (int kt = 0; kt < KT; kt++) {
        const int stage = kt % STAGES;
        asm volatile("cp.async.wait_group 1;" ::: "memory");
        __syncthreads();
        const int kn = kt + 2;
        if (kn < KT) issue(kn, kn % STAGES);
        asm volatile("cp.async.commit_group;" ::: "memory");

        const f16* sA = smem + stage * STAGE_ELEMS;
        const f16* sB = sA + A_ELEMS;
#pragma unroll
        for (int ks = 0; ks < 4; ks++) {
            const int kc = ks * 16;
            uint32_t af[4][4], bf[8][2];
#pragma unroll
            for (int i = 0; i < 4; i++)
                ldsm4(af[i], sptr(sA + a_off + i * 16 * ROW_ELEMS + kc));
#pragma unroll
            for (int jj = 0; jj < 4; jj++) {
                uint32_t r[4];
                ldsm4(r, sptr(sB + b_off + jj * 16 * ROW_ELEMS + kc));
                bf[2 * jj][0] = r[0]; bf[2 * jj][1] = r[1];
                bf[2 * jj + 1][0] = r[2]; bf[2 * jj + 1][1] = r[3];
            }
#pragma unroll
            for (int i = 0; i < 4; i++)
#pragma unroll
                for (int j = 0; j < 8; j++)
                    mma_f16acc(ch[i][j], af[i], bf[j]);
        }

        // promote chunk (K=256) into f32 acc via one HMMA per tile
        if ((kt & 3) == 3) {
#pragma unroll
            for (int i = 0; i < 4; i++)
#pragma unroll
                for (int j = 0; j < 8; j++) {
                    uint32_t aP[4] = {ch[i][j][0], ch[i][j][1], 0u, 0u};
                    uint32_t bP[2] = {bId, 0u};
                    mma_f32(acc[i][j], aP, bP);
                    ch[i][j][0] = 0u; ch[i][j][1] = 0u;
                }
        }
    }

    // ---------------- epilogue ----------------
    const float alpha = __ldg(sumAbs) * invCnt;
    const int r0 = bm * TM + wm * 64 + (lane >> 2);
    const int c0 = bn * TN + wn * 64 + (lane & 3) * 2;
#pragma unroll
    for (int i = 0; i < 4; i++) {
#pragma unroll
        for (int j = 0; j < 8; j++) {
            int row = r0 + i * 16;
            int col = c0 + j * 8;
            float bx = __ldg(bias + col), by = __ldg(bias + col + 1);
            float v00 = acc[i][j][0] * alpha + bx;
            float v01 = acc[i][j][1] * alpha + by;
            float v10 = acc[i][j][2] * alpha + bx;
            float v11 = acc[i][j][3] * alpha + by;
            if (EPI == 0) {
                v00 = fmaxf(v00, 0.f); v01 = fmaxf(v01, 0.f);
                v10 = fmaxf(v10, 0.f); v11 = fmaxf(v11, 0.f);
                size_t i0 = (size_t)row * N + col;
                size_t i1 = (size_t)(row + 8) * N + col;
                *reinterpret_cast<__half2*>(oH + i0) =
                    __halves2half2(__float2half(v00), __float2half(v01));
                *reinterpret_cast<__half2*>(oH + i1) =
                    __halves2half2(__float2half(v10), __float2half(v11));
            } else {
                float2 s0, s1;
                s0.x = 1.f / (1.f + __expf(-v00));
                s0.y = 1.f / (1.f + __expf(-v01));
                s1.x = 1.f / (1.f + __expf(-v10));
                s1.y = 1.f / (1.f + __expf(-v11));
                *reinterpret_cast<float2*>(oF + (size_t)row * N + col)       = s0;
                *reinterpret_cast<float2*>(oF + (size_t)(row + 8) * N + col) = s1;
            }
        }
    }
}

// ---------------- host launch ----------------
extern "C" void kernel_launch(void* const* d_in, const int* in_sizes, int n_in,
                              void* d_out, int out_size) {
    const float* x  = (const float*)d_in[0];
    const float* w1 = (const float*)d_in[1];
    const float* b1 = (const float*)d_in[2];
    const float* w2 = (const float*)d_in[3];
    const float* b2 = (const float*)d_in[4];
    const float* w3 = (const float*)d_in[5];
    const float* b3 = (const float*)d_in[6];

    void *pw1, *pw2, *pw3, *pa, *pb, *psum;
    cudaGetSymbolAddress(&pw1, g_w1s);
    cudaGetSymbolAddress(&pw2, g_w2s);
    cudaGetSymbolAddress(&pw3, g_w3s);
    cudaGetSymbolAddress(&pa, g_a);
    cudaGetSymbolAddress(&pb, g_b);
    cudaGetSymbolAddress(&psum, g_sum);
    float* sum = (float*)psum;

    sign_reduce_kernel<<<2048, 256>>>((const float4*)w1, (__half2*)pw1,
                                      HIDDEN * IN_SIZE / 4, 0);
    sign_reduce_kernel<<<2048, 256>>>((const float4*)w2, (__half2*)pw2,
                                      HIDDEN * HIDDEN / 4, 1);
    sign_reduce_kernel<<<2048, 256>>>((const float4*)w3, (__half2*)pw3,
                                      OUT_SIZE * HIDDEN / 4, 2);
    finalize_sum_kernel<<<3, 1024>>>();

    convert_kernel<<<2048, 256>>>((const float4*)x, (__half2*)pa, BATCH * IN_SIZE / 4);

    cudaFuncSetAttribute(gemm_bwn<0>, cudaFuncAttributeMaxDynamicSharedMemorySize, SMEM_BYTES);
    cudaFuncSetAttribute(gemm_bwn<1>, cudaFuncAttributeMaxDynamicSharedMemorySize, SMEM_BYTES);

    gemm_bwn<0><<<dim3(HIDDEN / TN, BATCH / TM), 256, SMEM_BYTES>>>(
        (const f16*)pa, (const f16*)pw1, b1, sum + 0,
        1.0f / ((float)HIDDEN * (float)IN_SIZE),
        IN_SIZE, HIDDEN, (f16*)pb, nullptr);

    gemm_bwn<0><<<dim3(HIDDEN / TN, BATCH / TM), 256, SMEM_BYTES>>>(
        (const f16*)pb, (const f16*)pw2, b2, sum + 1,
        1.0f / ((float)HIDDEN * (float)HIDDEN),
        HIDDEN, HIDDEN, (f16*)pa, nullptr);

    gemm_bwn<1><<<dim3(OUT_SIZE / TN, BATCH / TM), 256, SMEM_BYTES>>>(
        (const f16*)pa, (const f16*)pw3, b3, sum + 2,
        1.0f / ((float)OUT_SIZE * (float)HIDDEN),
        HIDDEN, OUT_SIZE, nullptr, (float*)d_out);
}

// round 8
// speedup vs baseline: 1.0293x; 1.0293x over previous
#include <cuda_runtime.h>
#include <cuda_fp16.h>
#include <cstdint>

using f16 = __half;

// Problem dims
constexpr int BATCH    = 8192;
constexpr int IN_SIZE  = 4096;
constexpr int HIDDEN   = 4096;
constexpr int OUT_SIZE = 1024;

// GEMM tiling: CTA tile 256x128, 16 warps (4x4), warp tile 64x32, BK=64
constexpr int TM = 256;
constexpr int TN = 128;
constexpr int BK = 64;
constexpr int STAGES = 3;
constexpr int ROW_ELEMS  = 72;                    // 64 data + 8 pad f16 (144B pitch)
constexpr int A_ELEMS = TM * ROW_ELEMS;           // 18432
constexpr int B_ELEMS = TN * ROW_ELEMS;           // 9216
constexpr int STAGE_ELEMS = A_ELEMS + B_ELEMS;    // 27648
constexpr int SMEM_BYTES = STAGES * STAGE_ELEMS * 2;  // 165888 B

// ---------------- static device scratch ----------------
__device__ f16 g_w1s[HIDDEN * IN_SIZE];
__device__ f16 g_w2s[HIDDEN * HIDDEN];
__device__ f16 g_w3s[OUT_SIZE * HIDDEN];
__device__ f16 g_a[BATCH * IN_SIZE];
__device__ f16 g_b[BATCH * HIDDEN];
__device__ float g_part[3 * 2048];
__device__ float g_sum[3];

// ---------------- PTX helpers ----------------
__device__ __forceinline__ uint32_t sptr(const void* p) {
    return (uint32_t)__cvta_generic_to_shared(p);
}
__device__ __forceinline__ void cp16(const f16* dst_smem, const f16* src_gmem) {
    uint32_t d = sptr(dst_smem);
    asm volatile("cp.async.cg.shared.global [%0], [%1], 16;\n" :: "r"(d), "l"(src_gmem));
}
__device__ __forceinline__ void ldsm4(uint32_t* r, uint32_t addr) {
    asm volatile("ldmatrix.sync.aligned.m8n8.x4.shared.b16 {%0,%1,%2,%3}, [%4];"
                 : "=r"(r[0]), "=r"(r[1]), "=r"(r[2]), "=r"(r[3]) : "r"(addr));
}
__device__ __forceinline__ void mma_f16(float* d, const uint32_t* a, const uint32_t* b) {
    asm volatile(
        "mma.sync.aligned.m16n8k16.row.col.f32.f16.f16.f32 "
        "{%0,%1,%2,%3}, {%4,%5,%6,%7}, {%8,%9}, {%0,%1,%2,%3};"
        : "+f"(d[0]), "+f"(d[1]), "+f"(d[2]), "+f"(d[3])
        : "r"(a[0]), "r"(a[1]), "r"(a[2]), "r"(a[3]), "r"(b[0]), "r"(b[1]));
}

// ---------------- prep kernels ----------------
__global__ void sign_reduce_kernel(const float4* __restrict__ w4,
                                   __half2* __restrict__ ws2,
                                   int n4, int layer) {
    float s = 0.f;
    for (int i = blockIdx.x * blockDim.x + threadIdx.x; i < n4; i += gridDim.x * blockDim.x) {
        float4 v = w4[i];
        s += fabsf(v.x) + fabsf(v.y) + fabsf(v.z) + fabsf(v.w);
        f16 s0 = __float2half((v.x > 0.f) ? 1.f : ((v.x < 0.f) ? -1.f : 0.f));
        f16 s1 = __float2half((v.y > 0.f) ? 1.f : ((v.y < 0.f) ? -1.f : 0.f));
        f16 s2 = __float2half((v.z > 0.f) ? 1.f : ((v.z < 0.f) ? -1.f : 0.f));
        f16 s3 = __float2half((v.w > 0.f) ? 1.f : ((v.w < 0.f) ? -1.f : 0.f));
        ws2[2 * i]     = __halves2half2(s0, s1);
        ws2[2 * i + 1] = __halves2half2(s2, s3);
    }
    __shared__ float red[256];
    red[threadIdx.x] = s;
    __syncthreads();
    for (int o = 128; o > 0; o >>= 1) {
        if (threadIdx.x < o) red[threadIdx.x] += red[threadIdx.x + o];
        __syncthreads();
    }
    if (threadIdx.x == 0) g_part[layer * 2048 + blockIdx.x] = red[0];
}

__global__ void finalize_sum_kernel() {
    __shared__ float red[1024];
    int l = blockIdx.x, t = threadIdx.x;
    red[t] = g_part[l * 2048 + t] + g_part[l * 2048 + 1024 + t];
    __syncthreads();
    for (int o = 512; o > 0; o >>= 1) {
        if (t < o) red[t] += red[t + o];
        __syncthreads();
    }
    if (t == 0) g_sum[l] = red[0];
}

__global__ void convert_kernel(const float4* __restrict__ x4,
                               __half2* __restrict__ h2, int n4) {
    for (int i = blockIdx.x * blockDim.x + threadIdx.x; i < n4; i += gridDim.x * blockDim.x) {
        float4 v = x4[i];
        h2[2 * i]     = __halves2half2(__float2half(v.x), __float2half(v.y));
        h2[2 * i + 1] = __halves2half2(__float2half(v.z), __float2half(v.w));
    }
}

// ---------------- fused binarized GEMM (512 thr, 4x4 warps, 64x32 warp tile) ----------------
template <int EPI>
__global__ void __launch_bounds__(512, 1) gemm_bwn(
    const f16* __restrict__ A, const f16* __restrict__ Bs,
    const float* __restrict__ bias, const float* __restrict__ sumAbs, float invCnt,
    int K, int N,
    f16* __restrict__ oH, float* __restrict__ oF) {
    extern __shared__ f16 smem[];
    const int tid  = threadIdx.x;
    const int lane = tid & 31;
    const int warp = tid >> 5;
    const int wm = warp & 3;   // 4 warp-rows of 64
    const int wn = warp >> 2;  // 4 warp-cols of 32
    const int bm = blockIdx.y, bn = blockIdx.x;
    const int KT = K / BK;

    const f16* gA = A  + (size_t)bm * TM * K;
    const f16* gB = Bs + (size_t)bn * TN * K;

    const int crow = tid >> 3;        // 0..63
    const int ccol = (tid & 7) * 8;   // 16B chunks (64 elems/row)

    auto issue = [&](int kt, int stage) {
        f16* sa = smem + stage * STAGE_ELEMS;
        f16* sb = sa + A_ELEMS;
        const int kof = kt * BK;
#pragma unroll
        for (int rr = 0; rr < 4; rr++) {
            const int row = rr * 64 + crow;
            cp16(sa + row * ROW_ELEMS + ccol, gA + (size_t)row * K + kof + ccol);
        }
#pragma unroll
        for (int rr = 0; rr < 2; rr++) {
            const int row = rr * 64 + crow;
            cp16(sb + row * ROW_ELEMS + ccol, gB + (size_t)row * K + kof + ccol);
        }
    };

    float acc[4][4][4];
#pragma unroll
    for (int i = 0; i < 4; i++)
#pragma unroll
        for (int j = 0; j < 4; j++)
#pragma unroll
            for (int v = 0; v < 4; v++) acc[i][j][v] = 0.f;

    const int a_off = (wm * 64 + (lane & 15)) * ROW_ELEMS + (lane >> 4) * 8;
    const int b_off = (wn * 32 + ((lane >> 4) & 1) * 8 + (lane & 7)) * ROW_ELEMS
                    + ((lane >> 3) & 1) * 8;

    issue(0, 0);
    asm volatile("cp.async.commit_group;" ::: "memory");
    issue(1, 1);
    asm volatile("cp.async.commit_group;" ::: "memory");

    for (int kt = 0; kt < KT; kt++) {
        const int stage = kt % STAGES;
        asm volatile("cp.async.wait_group 1;" ::: "memory");
        __syncthreads();
        const int kn = kt + 2;
        if (kn < KT) issue(kn, kn % STAGES);
        asm volatile("cp.async.commit_group;" ::: "memory");

        const f16* sA = smem + stage * STAGE_ELEMS;
        const f16* sB = sA + A_ELEMS;
#pragma unroll
        for (int ks = 0; ks < 4; ks++) {
            const int kc = ks * 16;
            uint32_t af[4][4], bf[4][2];
#pragma unroll
            for (int i = 0; i < 4; i++)
                ldsm4(af[i], sptr(sA + a_off + i * 16 * ROW_ELEMS + kc));
#pragma unroll
            for (int jj = 0; jj < 2; jj++) {
                uint32_t r[4];
                ldsm4(r, sptr(sB + b_off + jj * 16 * ROW_ELEMS + kc));
                bf[2 * jj][0] = r[0]; bf[2 * jj][1] = r[1];
                bf[2 * jj + 1][0] = r[2]; bf[2 * jj + 1][1] = r[3];
            }
#pragma unroll
            for (int i = 0; i < 4; i++)
#pragma unroll
                for (int j = 0; j < 4; j++)
                    mma_f16(acc[i][j], af[i], bf[j]);
        }
    }

    // ---------------- epilogue ----------------
    const float alpha = __ldg(sumAbs) * invCnt;
    const int r0 = bm * TM + wm * 64 + (lane >> 2);
    const int c0 = bn * TN + wn * 32 + (lane & 3) * 2;
#pragma unroll
    for (int i = 0; i < 4; i++) {
#pragma unroll
        for (int j = 0; j < 4; j++) {
            int row = r0 + i * 16;
            int col = c0 + j * 8;
            float bx = __ldg(bias + col), by = __ldg(bias + col + 1);
            float v00 = acc[i][j][0] * alpha + bx;
            float v01 = acc[i][j][1] * alpha + by;
            float v10 = acc[i][j][2] * alpha + bx;
            float v11 = acc[i][j][3] * alpha + by;
            if (EPI == 0) {
                v00 = fmaxf(v00, 0.f); v01 = fmaxf(v01, 0.f);
                v10 = fmaxf(v10, 0.f); v11 = fmaxf(v11, 0.f);
                size_t i0 = (size_t)row * N + col;
                size_t i1 = (size_t)(row + 8) * N + col;
                *reinterpret_cast<__half2*>(oH + i0) =
                    __halves2half2(__float2half(v00), __float2half(v01));
                *reinterpret_cast<__half2*>(oH + i1) =
                    __halves2half2(__float2half(v10), __float2half(v11));
            } else {
                float2 s0, s1;
                s0.x = 1.f / (1.f + __expf(-v00));
                s0.y = 1.f / (1.f + __expf(-v01));
                s1.x = 1.f / (1.f + __expf(-v10));
                s1.y = 1.f / (1.f + __expf(-v11));
                *reinterpret_cast<float2*>(oF + (size_t)row * N + col)       = s0;
                *reinterpret_cast<float2*>(oF + (size_t)(row + 8) * N + col) = s1;
            }
        }
    }
}

// ---------------- host launch ----------------
extern "C" void kernel_launch(void* const* d_in, const int* in_sizes, int n_in,
                              void* d_out, int out_size) {
    const float* x  = (const float*)d_in[0];
    const float* w1 = (const float*)d_in[1];
    const float* b1 = (const float*)d_in[2];
    const float* w2 = (const float*)d_in[3];
    const float* b2 = (const float*)d_in[4];
    const float* w3 = (const float*)d_in[5];
    const float* b3 = (const float*)d_in[6];

    void *pw1, *pw2, *pw3, *pa, *pb, *psum;
    cudaGetSymbolAddress(&pw1, g_w1s);
    cudaGetSymbolAddress(&pw2, g_w2s);
    cudaGetSymbolAddress(&pw3, g_w3s);
    cudaGetSymbolAddress(&pa, g_a);
    cudaGetSymbolAddress(&pb, g_b);
    cudaGetSymbolAddress(&psum, g_sum);
    float* sum = (float*)psum;

    sign_reduce_kernel<<<2048, 256>>>((const float4*)w1, (__half2*)pw1,
                                      HIDDEN * IN_SIZE / 4, 0);
    sign_reduce_kernel<<<2048, 256>>>((const float4*)w2, (__half2*)pw2,
                                      HIDDEN * HIDDEN / 4, 1);
    sign_reduce_kernel<<<2048, 256>>>((const float4*)w3, (__half2*)pw3,
                                      OUT_SIZE * HIDDEN / 4, 2);
    finalize_sum_kernel<<<3, 1024>>>();

    convert_kernel<<<2048, 256>>>((const float4*)x, (__half2*)pa, BATCH * IN_SIZE / 4);

    cudaFuncSetAttribute(gemm_bwn<0>, cudaFuncAttributeMaxDynamicSharedMemorySize, SMEM_BYTES);
    cudaFuncSetAttribute(gemm_bwn<1>, cudaFuncAttributeMaxDynamicSharedMemorySize, SMEM_BYTES);

    gemm_bwn<0><<<dim3(HIDDEN / TN, BATCH / TM), 512, SMEM_BYTES>>>(
        (const f16*)pa, (const f16*)pw1, b1, sum + 0,
        1.0f / ((float)HIDDEN * (float)IN_SIZE),
        IN_SIZE, HIDDEN, (f16*)pb, nullptr);

    gemm_bwn<0><<<dim3(HIDDEN / TN, BATCH / TM), 512, SMEM_BYTES>>>(
        (const f16*)pb, (const f16*)pw2, b2, sum + 1,
        1.0f / ((float)HIDDEN * (float)HIDDEN),
        HIDDEN, HIDDEN, (f16*)pa, nullptr);

    gemm_bwn<1><<<dim3(OUT_SIZE / TN, BATCH / TM), 512, SMEM_BYTES>>>(
        (const f16*)pa, (const f16*)pw3, b3, sum + 2,
        1.0f / ((float)OUT_SIZE * (float)HIDDEN),
        HIDDEN, OUT_SIZE, nullptr, (float*)d_out);
}